// round 9
// baseline (speedup 1.0000x reference)
#include <cuda_runtime.h>
#include <cstdint>
#include <cstddef>
#include <math.h>

static constexpr int Bn = 8;
static constexpr int Sn = 2048;
static constexpr int Dn = 384;
static constexpr int Hn = 6;
static constexpr int DHn = 64;
static constexpr int BSn = Bn * Sn;   // 16384
static constexpr int BHn = Bn * Hn;   // 48
static constexpr int NC = Sn / 64;    // 32 chunks

__device__ float g_out [BSn * Dn];
__device__ float g_left[BSn * Dn];
__device__ float g_xc  [BSn * Dn];
__device__ float g_q   [BSn * Dn];
__device__ float g_k   [BSn * Dn];
__device__ float g_v   [BSn * Dn];
__device__ float g_ig  [BSn * Hn];
__device__ float g_fg  [BSn * Hn];
__device__ float g_fe  [BHn * Sn];
__device__ float g_ie  [BHn * Sn];
__device__ float g_m   [BHn * Sn];
__device__ float g_rd  [BHn * Sn];
__device__ float g_h   [(size_t)BHn * Sn * DHn];
__device__ float g_G   [(size_t)BHn * NC * DHn * DHn];
__device__ float g_SC  [BHn * NC * 4];
__device__ float g_prod[BSn * Dn];

__device__ __forceinline__ float warp_sum(float v) {
    #pragma unroll
    for (int o = 16; o > 0; o >>= 1) v += __shfl_xor_sync(0xffffffffu, v, o);
    return v;
}
__device__ __forceinline__ float cvt_tf32(float x) {
    uint32_t o;
    asm("cvt.rna.tf32.f32 %0, %1;" : "=r"(o) : "f"(x));
    return __uint_as_float(o);
}
__device__ __forceinline__ void mma_tf32(float* d, const uint32_t* a, const uint32_t* b) {
    asm volatile(
        "mma.sync.aligned.m16n8k8.row.col.f32.tf32.tf32.f32 "
        "{%0,%1,%2,%3}, {%4,%5,%6,%7}, {%8,%9}, {%0,%1,%2,%3};"
        : "+f"(d[0]), "+f"(d[1]), "+f"(d[2]), "+f"(d[3])
        : "r"(a[0]), "r"(a[1]), "r"(a[2]), "r"(a[3]), "r"(b[0]), "r"(b[1]));
}
__device__ __forceinline__ void cp_async16(void* smem_dst, const void* gsrc) {
    uint32_t dst = (uint32_t)__cvta_generic_to_shared(smem_dst);
    asm volatile("cp.async.ca.shared.global [%0], [%1], 16;" :: "r"(dst), "l"(gsrc));
}

// 1) LayerNorm (eps = 384)
__global__ void ln_kernel(const float* __restrict__ x, const float* __restrict__ g,
                          const float* __restrict__ b, float* __restrict__ out) {
    int w = threadIdx.x >> 5, lane = threadIdx.x & 31;
    int row = blockIdx.x * 4 + w;
    const float* xr = x + (size_t)row * Dn;
    float vals[12];
    #pragma unroll
    for (int p = 0; p < 3; p++) {
        float4 t = *reinterpret_cast<const float4*>(xr + (lane + 32 * p) * 4);
        vals[p*4+0]=t.x; vals[p*4+1]=t.y; vals[p*4+2]=t.z; vals[p*4+3]=t.w;
    }
    float s = 0.f;
    #pragma unroll
    for (int i = 0; i < 12; i++) s += vals[i];
    float mu = warp_sum(s) * (1.0f / Dn);
    float ss = 0.f;
    #pragma unroll
    for (int i = 0; i < 12; i++) { vals[i] -= mu; ss += vals[i]*vals[i]; }
    float rs = rsqrtf(warp_sum(ss) * (1.0f / Dn) + 384.0f);
    float* orow = out + (size_t)row * Dn;
    #pragma unroll
    for (int p = 0; p < 3; p++) {
        int c = (lane + 32 * p) * 4;
        float4 t;
        t.x = vals[p*4+0]*rs*g[c+0]+b[c+0]; t.y = vals[p*4+1]*rs*g[c+1]+b[c+1];
        t.z = vals[p*4+2]*rs*g[c+2]+b[c+2]; t.w = vals[p*4+3]*rs*g[c+3]+b[c+3];
        *reinterpret_cast<float4*>(orow + c) = t;
    }
}

// 2) tf32 GEMM, cp.async double-buffered. BM=128 BN=64 BK=16, 8 warps.
__global__ void gemm_tf32(const float* __restrict__ A, const float* __restrict__ W,
                          const float* __restrict__ bias, float* __restrict__ Cout,
                          const float* __restrict__ addend, float scale,
                          const int* __restrict__ flipPtr) {
    constexpr int K = 384, N = 384;
    constexpr int LDA = 20;
    __shared__ float As[2][128 * LDA];
    __shared__ float Bs[2][64 * LDA];
    int tid = threadIdx.x;
    int lane = tid & 31, wid = tid >> 5;
    int warp_m = wid & 3, warp_n = wid >> 2;
    int m0 = blockIdx.x * 128, n0 = blockIdx.y * 64;
    int gq = lane >> 2, tg = lane & 3;
    float acc[2][4][4];
    #pragma unroll
    for (int a = 0; a < 2; a++)
        #pragma unroll
        for (int b = 0; b < 4; b++)
            #pragma unroll
            for (int c = 0; c < 4; c++) acc[a][b][c] = 0.f;

    auto issue = [&](int buf, int k0) {
        #pragma unroll
        for (int p = 0; p < 2; p++) {
            int idx = tid + 256 * p;
            int m = idx >> 2, c4 = (idx & 3) << 2;
            cp_async16(&As[buf][m * LDA + c4], A + (size_t)(m0 + m) * K + k0 + c4);
        }
        {
            int n = tid >> 2, c4 = (tid & 3) << 2;
            cp_async16(&Bs[buf][n * LDA + c4], W + (size_t)(n0 + n) * K + k0 + c4);
        }
        asm volatile("cp.async.commit_group;");
    };

    issue(0, 0);
    constexpr int NIT = K / 16;  // 24
    for (int it = 0; it < NIT; it++) {
        if (it + 1 < NIT) {
            issue((it + 1) & 1, (it + 1) * 16);
            asm volatile("cp.async.wait_group 1;");
        } else {
            asm volatile("cp.async.wait_group 0;");
        }
        __syncthreads();
        const float* Ab = As[it & 1];
        const float* Bb = Bs[it & 1];
        #pragma unroll
        for (int kk = 0; kk < 16; kk += 8) {
            uint32_t af[2][4], bfr[4][2];
            #pragma unroll
            for (int mt = 0; mt < 2; mt++) {
                int mr = warp_m * 32 + mt * 16 + gq;
                af[mt][0] = __float_as_uint(Ab[ mr      * LDA + kk + tg]);
                af[mt][1] = __float_as_uint(Ab[(mr + 8) * LDA + kk + tg]);
                af[mt][2] = __float_as_uint(Ab[ mr      * LDA + kk + 4 + tg]);
                af[mt][3] = __float_as_uint(Ab[(mr + 8) * LDA + kk + 4 + tg]);
            }
            #pragma unroll
            for (int nt = 0; nt < 4; nt++) {
                int nr = warp_n * 32 + nt * 8 + gq;
                bfr[nt][0] = __float_as_uint(Bb[nr * LDA + kk + tg]);
                bfr[nt][1] = __float_as_uint(Bb[nr * LDA + kk + 4 + tg]);
            }
            #pragma unroll
            for (int mt = 0; mt < 2; mt++)
                #pragma unroll
                for (int nt = 0; nt < 4; nt++) mma_tf32(acc[mt][nt], af[mt], bfr[nt]);
        }
        __syncthreads();
    }

    int fl = flipPtr ? *flipPtr : 0;
    #pragma unroll
    for (int mt = 0; mt < 2; mt++) {
        int r0 = m0 + warp_m * 32 + mt * 16 + gq;
        int r1 = r0 + 8;
        #pragma unroll
        for (int nt = 0; nt < 4; nt++) {
            int col = n0 + warp_n * 32 + nt * 8 + tg * 2;
            float b0v = bias[col], b1v = bias[col + 1];
            float v00 = (acc[mt][nt][0] + b0v) * scale;
            float v01 = (acc[mt][nt][1] + b1v) * scale;
            float v10 = (acc[mt][nt][2] + b0v) * scale;
            float v11 = (acc[mt][nt][3] + b1v) * scale;
            if (addend) {
                v00 += addend[(size_t)r0 * N + col];
                v01 += addend[(size_t)r0 * N + col + 1];
                v10 += addend[(size_t)r1 * N + col];
                v11 += addend[(size_t)r1 * N + col + 1];
            }
            int ms0 = r0, ms1 = r1;
            if (fl) {
                ms0 = (r0 & ~2047) + (Sn - 1 - (r0 & 2047));
                ms1 = (r1 & ~2047) + (Sn - 1 - (r1 & 2047));
            }
            *reinterpret_cast<float2*>(Cout + (size_t)ms0 * N + col) = make_float2(v00, v01);
            *reinterpret_cast<float2*>(Cout + (size_t)ms1 * N + col) = make_float2(v10, v11);
        }
    }
}

// 3) causal depthwise conv (K=4) + SiLU
__global__ void conv_kernel(const float* __restrict__ left, const float* __restrict__ cw,
                            const float* __restrict__ cb, float* __restrict__ xc) {
    int bt = blockIdx.x;
    int b = bt >> 11, t = bt & 2047;
    #pragma unroll
    for (int p = 0; p < 3; p++) {
        int d = threadIdx.x + 128 * p;
        float acc = cb[d];
        #pragma unroll
        for (int j = 0; j < 4; j++) {
            int tt = t - 3 + j;
            if (tt >= 0) acc += cw[d*4+j] * left[((size_t)b*Sn + tt)*Dn + d];
        }
        xc[(size_t)bt*Dn + d] = acc / (1.0f + expf(-acc));
    }
}

// 4) ig / fg: warp-per-row, register dot products + warp reductions
__global__ void igfg_kernel(const float* __restrict__ left,
                            const float* __restrict__ Wi, const float* __restrict__ bi,
                            const float* __restrict__ Wf, const float* __restrict__ bf,
                            float* __restrict__ ig, float* __restrict__ fg) {
    __shared__ float sW[12 * 384];
    __shared__ float sA[8 * 384];
    int tid = threadIdx.x;      // 256
    int w = tid >> 5, lane = tid & 31;
    int row0 = blockIdx.x * 8;
    // stage weights (Wi rows 0-5, Wf rows 6-11)
    for (int i = tid; i < 1152; i += 256) {
        int o = i / 96, j = (i - o * 96) * 4;
        const float* src = (o < 6) ? (Wi + o * 384 + j) : (Wf + (o - 6) * 384 + j);
        *reinterpret_cast<float4*>(&sW[o * 384 + j]) = *reinterpret_cast<const float4*>(src);
    }
    // stage 8 rows
    for (int i = tid; i < 768; i += 256) {
        int r = i / 96, j = (i - r * 96) * 4;
        *reinterpret_cast<float4*>(&sA[r * 384 + j]) =
            *reinterpret_cast<const float4*>(left + ((size_t)row0 + r) * 384 + j);
    }
    __syncthreads();
    float a[12];
    #pragma unroll
    for (int p = 0; p < 3; p++) {
        float4 t = *reinterpret_cast<const float4*>(&sA[w * 384 + lane * 12 + p * 4]);
        a[p*4+0]=t.x; a[p*4+1]=t.y; a[p*4+2]=t.z; a[p*4+3]=t.w;
    }
    float res[12];
    #pragma unroll
    for (int o = 0; o < 12; o++) {
        float s = 0.f;
        #pragma unroll
        for (int p = 0; p < 3; p++) {
            float4 t = *reinterpret_cast<const float4*>(&sW[o * 384 + lane * 12 + p * 4]);
            s += a[p*4+0]*t.x + a[p*4+1]*t.y + a[p*4+2]*t.z + a[p*4+3]*t.w;
        }
        res[o] = warp_sum(s);
    }
    if (lane == 0) {
        int row = row0 + w;
        #pragma unroll
        for (int o = 0; o < 6; o++) ig[(size_t)row * Hn + o] = res[o] + bi[o];
        #pragma unroll
        for (int o = 0; o < 6; o++) {
            float z = res[6 + o] + bf[o];
            fg[(size_t)row * Hn + o] = fminf(z, 0.f) - log1pf(expf(-fabsf(z)));
        }
    }
}

// 5) gates: closed-form m (stored); fe/ie; n-scan + 1/den (k,q staged in smem)
__global__ void gates_kernel(const float* __restrict__ ig, const float* __restrict__ fg,
                             const float* __restrict__ k, const float* __restrict__ q,
                             float* __restrict__ fe, float* __restrict__ ie,
                             float* __restrict__ mOut, float* __restrict__ rd) {
    __shared__ float sh[64*68*2 + 128];
    float* kbuf = sh;
    float* qbuf = sh + 64*68;
    float* fes  = sh + 64*68*2;
    float* ies  = fes + 64;
    float* sF = sh; float* sG = sh + 256; float* oFp = sh + 512; float* pGp = sh + 768;

    int bh = blockIdx.x;
    int b = bh / Hn, h = bh - b * Hn;
    int tid = threadIdx.x; // 256
    const size_t gbase = (size_t)bh * Sn;

    float fgl[8], igl[8], Fl[8], Gl[8];
    int tbase = tid * 8;
    #pragma unroll
    for (int j = 0; j < 8; j++) {
        int t = tbase + j;
        fgl[j] = fg[((size_t)b*Sn + t)*Hn + h];
        igl[j] = ig[((size_t)b*Sn + t)*Hn + h];
    }
    float F = 0.f, G = -INFINITY;
    #pragma unroll
    for (int j = 0; j < 8; j++) {
        F += fgl[j]; Fl[j] = F;
        G = fmaxf(G, igl[j] - F); Gl[j] = G;
    }
    sF[tid] = F; sG[tid] = G;
    __syncthreads();
    if (tid == 0) {
        float aF = 0.f, aG = -INFINITY;
        for (int i = 0; i < 256; i++) {
            oFp[i] = aF; pGp[i] = aG;
            aG = fmaxf(aG, sG[i] - aF);
            aF += sF[i];
        }
    }
    __syncthreads();
    float oF = oFp[tid], pG = pGp[tid];
    float mp = oF + pG;
    #pragma unroll
    for (int j = 0; j < 8; j++) {
        float Ft = oF + Fl[j];
        float Gt = fmaxf(pG, Gl[j] - oF);
        float m = Ft + Gt;
        fe[gbase + tbase + j] = expf(fgl[j] + mp - m);
        ie[gbase + tbase + j] = expf(igl[j] - m);
        mOut[gbase + tbase + j] = m;
        mp = m;
    }
    __syncthreads();

    float nreg = 0.f;
    for (int t0 = 0; t0 < Sn; t0 += 64) {
        #pragma unroll
        for (int p = 0; p < 4; p++) {
            int idx = tid + 256 * p;            // 1024 float4 slots
            int tt = idx >> 4, j4 = (idx & 15) << 2;
            size_t go = ((size_t)b*Sn + t0 + tt)*Dn + h*DHn + j4;
            *reinterpret_cast<float4*>(&kbuf[tt*68 + j4]) = *reinterpret_cast<const float4*>(k + go);
            *reinterpret_cast<float4*>(&qbuf[tt*68 + j4]) = *reinterpret_cast<const float4*>(q + go);
        }
        if (tid < 64) fes[tid] = fe[gbase + t0 + tid];
        else if (tid < 128) ies[tid-64] = ie[gbase + t0 + tid - 64];
        __syncthreads();
        if (tid < 64) {
            #pragma unroll 4
            for (int tt = 0; tt < 64; tt++) {
                nreg = fes[tt] * nreg + ies[tt] * kbuf[tt*68 + tid];
                kbuf[tt*68 + tid] = nreg;
            }
        }
        __syncthreads();
        if (tid < 64) {
            float den = 0.f;
            #pragma unroll 8
            for (int j = 0; j < 64; j++) den += kbuf[tid*68 + j] * qbuf[tid*68 + j];
            rd[gbase + t0 + tid] = 1.0f / fmaxf(fabsf(den), 1.0f);
        }
        __syncthreads();
    }
}

// 6a) chunk phase A: log-space anchored scaling; S=tril(Q'K'^T), intra=S@V, G=V^T K'.
__global__ void chunkA(float* __restrict__ q, const float* __restrict__ k,
                       const float* __restrict__ v,
                       const float* __restrict__ ig, const float* __restrict__ fg,
                       const float* __restrict__ mArr,
                       float* __restrict__ hintra, float* __restrict__ Gout,
                       float* __restrict__ SC) {
    extern __shared__ float sm[];
    float* sQ = sm;              // 64*68 (later S)
    float* sK = sm + 64*68;
    float* sV = sm + 2*64*68;
    float* sfg = sm + 3*64*68;   // 64
    float* sig_ = sfg + 64;
    float* smv = sig_ + 64;
    float* sFl = smv + 64;
    float* sRow = sFl + 64;
    float* sCol = sRow + 64;
    float* sScal = sCol + 64;    // 4

    int c = blockIdx.x, bh = blockIdx.y;
    int b = bh / Hn, h = bh - b * Hn;
    int t0 = c * 64;
    int tid = threadIdx.x;       // 128
    int lane = tid & 31, w = tid >> 5;
    int gq = lane >> 2, tg = lane & 3;
    size_t gbase = (size_t)bh * Sn + t0;

    if (tid < 64) {
        int t = t0 + tid;
        sfg[tid]  = fg[((size_t)b*Sn + t)*Hn + h];
        sig_[tid] = ig[((size_t)b*Sn + t)*Hn + h];
        smv[tid]  = mArr[gbase + tid];
    }
    __syncthreads();
    if (tid == 0) {
        float Fl = 0.f, AA = -INFINITY;
        for (int i = 0; i < 64; i++) {
            Fl += sfg[i]; sFl[i] = Fl;
            AA = fmaxf(AA, sig_[i] - Fl);
        }
        float mT1 = smv[63];
        bool first = (c == 0);
        float Ac = first ? 0.f : mArr[gbase - 1];
        sScal[0] = first ? 0.f : expf(Ac - AA);              // s_c
        sScal[1] = first ? 0.f : expf(sFl[63] + Ac - mT1);   // PL
        sScal[2] = expf(AA + sFl[63] - mT1);                 // gfac
        sScal[3] = AA;
    }
    __syncthreads();
    if (tid < 64) {
        float AA = sScal[3];
        sRow[tid] = expf(sFl[tid] - smv[tid] + AA);
        sCol[tid] = expf(sig_[tid] - sFl[tid] - AA);
    }
    if (tid >= 64 && tid < 67) SC[(size_t)(bh*NC + c)*4 + (tid - 64)] = sScal[tid - 64];
    __syncthreads();

    {
        int i = tid >> 1, hf = tid & 1;
        size_t ro = ((size_t)b*Sn + t0 + i)*Dn + h*DHn + hf*32;
        float rsc = sRow[i];
        float csc = sCol[i];
        #pragma unroll
        for (int p = 0; p < 8; p++) {
            int j = hf*32 + p*4;
            float4 qv = *reinterpret_cast<const float4*>(q + ro + p*4);
            float4 kv = *reinterpret_cast<const float4*>(k + ro + p*4);
            float4 vv = *reinterpret_cast<const float4*>(v + ro + p*4);
            qv.x *= rsc; qv.y *= rsc; qv.z *= rsc; qv.w *= rsc;
            *reinterpret_cast<float4*>(q + ro + p*4) = qv;    // Q' in place
            sQ[i*68+j+0]=cvt_tf32(qv.x); sQ[i*68+j+1]=cvt_tf32(qv.y);
            sQ[i*68+j+2]=cvt_tf32(qv.z); sQ[i*68+j+3]=cvt_tf32(qv.w);
            sK[i*68+j+0]=cvt_tf32(kv.x*csc); sK[i*68+j+1]=cvt_tf32(kv.y*csc);
            sK[i*68+j+2]=cvt_tf32(kv.z*csc); sK[i*68+j+3]=cvt_tf32(kv.w*csc);
            sV[i*68+j+0]=cvt_tf32(vv.x); sV[i*68+j+1]=cvt_tf32(vv.y);
            sV[i*68+j+2]=cvt_tf32(vv.z); sV[i*68+j+3]=cvt_tf32(vv.w);
        }
    }
    __syncthreads();

    // GEMM1: S = Q' @ K'^T
    float accS[8][4];
    #pragma unroll
    for (int nt = 0; nt < 8; nt++)
        #pragma unroll
        for (int x = 0; x < 4; x++) accS[nt][x] = 0.f;
    int m0 = w * 16;
    #pragma unroll
    for (int kk = 0; kk < 64; kk += 8) {
        uint32_t af[4];
        af[0] = __float_as_uint(sQ[(m0+gq)*68 + kk+tg]);
        af[1] = __float_as_uint(sQ[(m0+gq+8)*68 + kk+tg]);
        af[2] = __float_as_uint(sQ[(m0+gq)*68 + kk+4+tg]);
        af[3] = __float_as_uint(sQ[(m0+gq+8)*68 + kk+4+tg]);
        #pragma unroll
        for (int nt = 0; nt < 8; nt++) {
            uint32_t bf[2];
            bf[0] = __float_as_uint(sK[(nt*8+gq)*68 + kk+tg]);
            bf[1] = __float_as_uint(sK[(nt*8+gq)*68 + kk+4+tg]);
            mma_tf32(accS[nt], af, bf);
        }
    }
    __syncthreads();
    #pragma unroll
    for (int nt = 0; nt < 8; nt++) {
        int r0 = m0 + gq, r1 = r0 + 8;
        int c0 = nt*8 + tg*2, c1 = c0 + 1;
        sQ[r0*68 + c0] = (c0 <= r0) ? cvt_tf32(accS[nt][0]) : 0.f;
        sQ[r0*68 + c1] = (c1 <= r0) ? cvt_tf32(accS[nt][1]) : 0.f;
        sQ[r1*68 + c0] = (c0 <= r1) ? cvt_tf32(accS[nt][2]) : 0.f;
        sQ[r1*68 + c1] = (c1 <= r1) ? cvt_tf32(accS[nt][3]) : 0.f;
    }
    __syncthreads();

    // GEMM2: intra = S @ V
    float accI[8][4];
    #pragma unroll
    for (int nt = 0; nt < 8; nt++)
        #pragma unroll
        for (int x = 0; x < 4; x++) accI[nt][x] = 0.f;
    #pragma unroll
    for (int kk = 0; kk < 64; kk += 8) {
        uint32_t af[4];
        af[0] = __float_as_uint(sQ[(m0+gq)*68 + kk+tg]);
        af[1] = __float_as_uint(sQ[(m0+gq+8)*68 + kk+tg]);
        af[2] = __float_as_uint(sQ[(m0+gq)*68 + kk+4+tg]);
        af[3] = __float_as_uint(sQ[(m0+gq+8)*68 + kk+4+tg]);
        #pragma unroll
        for (int nt = 0; nt < 8; nt++) {
            uint32_t bf[2];
            bf[0] = __float_as_uint(sV[(kk+tg)*68 + nt*8+gq]);
            bf[1] = __float_as_uint(sV[(kk+4+tg)*68 + nt*8+gq]);
            mma_tf32(accI[nt], af, bf);
        }
    }
    #pragma unroll
    for (int nt = 0; nt < 8; nt++) {
        int r0 = m0 + gq, r1 = r0 + 8;
        int c0 = nt*8 + tg*2;
        size_t o0 = (gbase + r0) * DHn + c0;
        size_t o1 = (gbase + r1) * DHn + c0;
        *reinterpret_cast<float2*>(hintra + o0) = make_float2(accI[nt][0], accI[nt][1]);
        *reinterpret_cast<float2*>(hintra + o1) = make_float2(accI[nt][2], accI[nt][3]);
    }

    // GEMM3: G = V^T @ K'
    float accG[8][4];
    #pragma unroll
    for (int nt = 0; nt < 8; nt++)
        #pragma unroll
        for (int x = 0; x < 4; x++) accG[nt][x] = 0.f;
    #pragma unroll
    for (int kk = 0; kk < 64; kk += 8) {
        uint32_t af[4];
        af[0] = __float_as_uint(sV[(kk+tg)*68 + m0+gq]);
        af[1] = __float_as_uint(sV[(kk+tg)*68 + m0+gq+8]);
        af[2] = __float_as_uint(sV[(kk+4+tg)*68 + m0+gq]);
        af[3] = __float_as_uint(sV[(kk+4+tg)*68 + m0+gq+8]);
        #pragma unroll
        for (int nt = 0; nt < 8; nt++) {
            uint32_t bf[2];
            bf[0] = __float_as_uint(sK[(kk+tg)*68 + nt*8+gq]);
            bf[1] = __float_as_uint(sK[(kk+4+tg)*68 + nt*8+gq]);
            mma_tf32(accG[nt], af, bf);
        }
    }
    size_t Gb = ((size_t)bh*NC + c) * DHn * DHn;
    #pragma unroll
    for (int nt = 0; nt < 8; nt++) {
        int r0 = m0 + gq, r1 = r0 + 8;
        int c0 = nt*8 + tg*2;
        *reinterpret_cast<float2*>(Gout + Gb + (size_t)r0*DHn + c0) = make_float2(accG[nt][0], accG[nt][1]);
        *reinterpret_cast<float2*>(Gout + Gb + (size_t)r1*DHn + c0) = make_float2(accG[nt][2], accG[nt][3]);
    }
}

// 6b) phase B: serial over chunks, 2 blocks per (b,h) split on v (C rows).
//     Ninter = s_c*(Q' @ C^T); h=(intra+Ninter)*rd; C = PL*C + gfac*G.
__global__ void chunkB(const float* __restrict__ qp, const float* __restrict__ Gin,
                       const float* __restrict__ SC, const float* __restrict__ rd,
                       float* __restrict__ hio) {
    __shared__ float sC[32*68];
    __shared__ float sQ[64*68];
    int bh = blockIdx.x >> 1;
    int half = blockIdx.x & 1;
    int b = bh / Hn, h = bh - b * Hn;
    int tid = threadIdx.x;  // 128
    int lane = tid & 31, w = tid >> 5;
    int gq = lane >> 2, tg = lane & 3;
    int m0 = w * 16;
    int rq = tid >> 1, hfq = tid & 1;   // Q staging
    int rc = tid >> 2, qf = tid & 3;    // C ownership: row rc (0..31), cols qf*16..

    float Creg[16];
    #pragma unroll
    for (int j = 0; j < 16; j++) Creg[j] = 0.f;
    for (int idx = tid; idx < 32*68; idx += 128) sC[idx] = 0.f;
    __syncthreads();

    for (int c = 0; c < NC; c++) {
        int t0 = c * 64;
        float s_c  = SC[(size_t)(bh*NC + c)*4 + 0];
        float PLc  = SC[(size_t)(bh*NC + c)*4 + 1];
        float gfac = SC[(size_t)(bh*NC + c)*4 + 2];
        {
            size_t ro = ((size_t)b*Sn + t0 + rq)*Dn + h*DHn + hfq*32;
            #pragma unroll
            for (int p = 0; p < 8; p++) {
                float4 qv = *reinterpret_cast<const float4*>(qp + ro + p*4);
                int j = hfq*32 + p*4;
                sQ[rq*68+j+0]=cvt_tf32(qv.x); sQ[rq*68+j+1]=cvt_tf32(qv.y);
                sQ[rq*68+j+2]=cvt_tf32(qv.z); sQ[rq*68+j+3]=cvt_tf32(qv.w);
            }
        }
        __syncthreads();
        // Ninter(local cols) = Q'(64x64) @ C^T(32x64)
        float acc[4][4];
        #pragma unroll
        for (int nt = 0; nt < 4; nt++)
            #pragma unroll
            for (int x = 0; x < 4; x++) acc[nt][x] = 0.f;
        #pragma unroll
        for (int kk = 0; kk < 64; kk += 8) {
            uint32_t af[4];
            af[0] = __float_as_uint(sQ[(m0+gq)*68 + kk+tg]);
            af[1] = __float_as_uint(sQ[(m0+gq+8)*68 + kk+tg]);
            af[2] = __float_as_uint(sQ[(m0+gq)*68 + kk+4+tg]);
            af[3] = __float_as_uint(sQ[(m0+gq+8)*68 + kk+4+tg]);
            #pragma unroll
            for (int nt = 0; nt < 4; nt++) {
                uint32_t bf[2];
                bf[0] = __float_as_uint(sC[(nt*8+gq)*68 + kk+tg]);
                bf[1] = __float_as_uint(sC[(nt*8+gq)*68 + kk+4+tg]);
                mma_tf32(acc[nt], af, bf);
            }
        }
        #pragma unroll
        for (int nt = 0; nt < 4; nt++) {
            int r0 = m0 + gq, r1 = r0 + 8;
            int c0 = half*32 + nt*8 + tg*2;
            size_t u0 = (size_t)bh*Sn + t0 + r0;
            size_t u1 = (size_t)bh*Sn + t0 + r1;
            float rd0 = rd[u0], rd1 = rd[u1];
            float2 i0 = *reinterpret_cast<const float2*>(hio + u0*DHn + c0);
            float2 i1 = *reinterpret_cast<const float2*>(hio + u1*DHn + c0);
            *reinterpret_cast<float2*>(hio + u0*DHn + c0) =
                make_float2((i0.x + s_c*acc[nt][0]) * rd0, (i0.y + s_c*acc[nt][1]) * rd0);
            *reinterpret_cast<float2*>(hio + u1*DHn + c0) =
                make_float2((i1.x + s_c*acc[nt][2]) * rd1, (i1.y + s_c*acc[nt][3]) * rd1);
        }
        __syncthreads();
        size_t Gb = ((size_t)bh*NC + c) * DHn * DHn + (size_t)(half*32 + rc)*DHn + qf*16;
        #pragma unroll
        for (int p = 0; p < 4; p++) {
            float4 gv = *reinterpret_cast<const float4*>(Gin + Gb + p*4);
            int j = p*4;
            Creg[j+0] = PLc * Creg[j+0] + gfac * gv.x;
            Creg[j+1] = PLc * Creg[j+1] + gfac * gv.y;
            Creg[j+2] = PLc * Creg[j+2] + gfac * gv.z;
            Creg[j+3] = PLc * Creg[j+3] + gfac * gv.w;
            int cc = qf*16 + j;
            sC[rc*68+cc+0]=cvt_tf32(Creg[j+0]); sC[rc*68+cc+1]=cvt_tf32(Creg[j+1]);
            sC[rc*68+cc+2]=cvt_tf32(Creg[j+2]); sC[rc*68+cc+3]=cvt_tf32(Creg[j+3]);
        }
        __syncthreads();
    }
}

// 7) GroupNorm + unflip + multiply by LN out
__global__ void gnprod_kernel(const float* __restrict__ hin,
                              const float* __restrict__ gn_g, const float* __restrict__ gn_b,
                              const float* __restrict__ outln,
                              const int* __restrict__ flipPtr,
                              float* __restrict__ prod) {
    int w = threadIdx.x >> 5, lane = threadIdx.x & 31;
    int u = blockIdx.x * 8 + w;
    int b = u / (Hn * Sn);
    int rem = u - b * (Hn * Sn);
    int h = rem / Sn, t = rem - h * Sn;
    float v0 = hin[(size_t)u*DHn + lane];
    float v1 = hin[(size_t)u*DHn + 32 + lane];
    float mu = warp_sum(v0 + v1) * (1.0f / DHn);
    float x0 = v0 - mu, x1 = v1 - mu;
    float rs = rsqrtf(warp_sum(x0*x0 + x1*x1) * (1.0f / DHn) + 1e-5f);
    int d0 = h*DHn + lane, d1 = d0 + 32;
    float hn0 = x0*rs*gn_g[d0] + gn_b[d0];
    float hn1 = x1*rs*gn_g[d1] + gn_b[d1];
    int s = (*flipPtr) ? (Sn - 1 - t) : t;
    size_t row = ((size_t)b*Sn + s) * Dn;
    prod[row + d0] = hn0 * outln[row + d0];
    prod[row + d1] = hn1 * outln[row + d1];
}

extern "C" void kernel_launch(void* const* d_in, const int* in_sizes, int n_in,
                              void* d_out, int out_size) {
    const float* x    = (const float*)d_in[0];
    const float* ln_g = (const float*)d_in[1];
    const float* ln_b = (const float*)d_in[2];
    const float* W2   = (const float*)d_in[5];
    const float* b2   = (const float*)d_in[6];
    const float* W3   = (const float*)d_in[7];
    const float* b3   = (const float*)d_in[8];
    const float* cw   = (const float*)d_in[9];
    const float* cb   = (const float*)d_in[10];
    const float* Wq   = (const float*)d_in[11];
    const float* bq   = (const float*)d_in[12];
    const float* Wk   = (const float*)d_in[13];
    const float* bk   = (const float*)d_in[14];
    const float* Wv   = (const float*)d_in[15];
    const float* bv   = (const float*)d_in[16];
    const float* Wi   = (const float*)d_in[17];
    const float* bi   = (const float*)d_in[18];
    const float* Wf   = (const float*)d_in[19];
    const float* bf   = (const float*)d_in[20];
    const float* gn_g = (const float*)d_in[21];
    const float* gn_b = (const float*)d_in[22];
    const int*   flip = (const int*)d_in[23];
    float* out = (float*)d_out;

    float *p_out, *p_left, *p_xc, *p_q, *p_k, *p_v, *p_ig, *p_fg,
          *p_fe, *p_ie, *p_m, *p_rd, *p_h, *p_G, *p_SC, *p_prod;
    cudaGetSymbolAddress((void**)&p_out,  g_out);
    cudaGetSymbolAddress((void**)&p_left, g_left);
    cudaGetSymbolAddress((void**)&p_xc,   g_xc);
    cudaGetSymbolAddress((void**)&p_q,    g_q);
    cudaGetSymbolAddress((void**)&p_k,    g_k);
    cudaGetSymbolAddress((void**)&p_v,    g_v);
    cudaGetSymbolAddress((void**)&p_ig,   g_ig);
    cudaGetSymbolAddress((void**)&p_fg,   g_fg);
    cudaGetSymbolAddress((void**)&p_fe,   g_fe);
    cudaGetSymbolAddress((void**)&p_ie,   g_ie);
    cudaGetSymbolAddress((void**)&p_m,    g_m);
    cudaGetSymbolAddress((void**)&p_rd,   g_rd);
    cudaGetSymbolAddress((void**)&p_h,    g_h);
    cudaGetSymbolAddress((void**)&p_G,    g_G);
    cudaGetSymbolAddress((void**)&p_SC,   g_SC);
    cudaGetSymbolAddress((void**)&p_prod, g_prod);

    cudaError_t attr_ok = cudaFuncSetAttribute(
        chunkA, cudaFuncAttributeMaxDynamicSharedMemorySize, 54560);
    (void)attr_ok;

    dim3 ggrid(BSn / 128, Dn / 64);

    ln_kernel<<<BSn / 4, 128>>>(x, ln_g, ln_b, p_out);
    gemm_tf32<<<ggrid, 256>>>(p_out, W2, b2, p_left, nullptr, 1.0f, flip);
    conv_kernel<<<BSn, 128>>>(p_left, cw, cb, p_xc);
    gemm_tf32<<<ggrid, 256>>>(p_xc,   Wq, bq, p_q, nullptr, 1.0f,   nullptr);
    gemm_tf32<<<ggrid, 256>>>(p_xc,   Wk, bk, p_k, nullptr, 0.125f, nullptr);
    gemm_tf32<<<ggrid, 256>>>(p_left, Wv, bv, p_v, nullptr, 1.0f,   nullptr);
    igfg_kernel<<<BSn / 8, 256>>>(p_left, Wi, bi, Wf, bf, p_ig, p_fg);
    gates_kernel<<<BHn, 256>>>(p_ig, p_fg, p_k, p_q, p_fe, p_ie, p_m, p_rd);
    chunkA<<<dim3(NC, BHn), 128, 54560>>>(p_q, p_k, p_v, p_ig, p_fg, p_m, p_h, p_G, p_SC);
    chunkB<<<BHn * 2, 128>>>(p_q, p_G, p_SC, p_rd, p_h);
    gnprod_kernel<<<(BHn * Sn) / 8, 256>>>(p_h, gn_g, gn_b, p_out, flip, p_prod);
    gemm_tf32<<<ggrid, 256>>>(p_prod, W3, b3, out, x, 1.0f, nullptr);
}